// round 7
// baseline (speedup 1.0000x reference)
#include <cuda_runtime.h>
#include <math.h>

#define B_ 4
#define N_ 8192

constexpr int   NBUCKET = 1024;
constexpr float RLO   = -6.0f;
constexpr float BWID  = 12.0f / NBUCKET;       // 0.01171875
constexpr float INVBW = NBUCKET / 12.0f;

constexpr int TPB       = 128;                 // threads per block (query + SL)
constexpr int QSEG      = 128;                 // queries per block
constexpr int QBLOCKS   = 2 * B_ * (N_ / QSEG);  // 512
constexpr int SL_BLOCKS = 160;
constexpr int FTPB      = 512;

// Scratch (write-once per call; no init needed, no atomics on globals).
__device__ float4 g_sorted[2][B_][N_];             // bucket-ordered points, .w=0
__device__ int    g_bstart[2][B_][NBUCKET + 1];    // bucket start offsets
__device__ float  g_part[3 * SL_BLOCKS];           // small-loss partials
__device__ float  g_qpart[QBLOCKS];                // per-block sum of sqrt(min d2)

// ---------------- K1: bucket build (counting sort by x0) ----------------
// 8 blocks: (cloud, batch). 1024 threads, 8 points each.
__global__ void build_kernel(const float* __restrict__ pred,
                             const float* __restrict__ targ) {
    __shared__ int sA[NBUCKET];
    __shared__ int sB[NBUCKET];
    const int tid   = threadIdx.x;
    const int cloud = blockIdx.x >> 2;
    const int b     = blockIdx.x & 3;
    const float* src = (cloud ? targ : pred) + b * N_ * 3;

    sA[tid] = 0;
    __syncthreads();

    float3 pt[8];
    int    bk[8];
#pragma unroll
    for (int i = 0; i < 8; i++) {
        int k = tid + i * NBUCKET;
        float x0 = src[k * 3], x1 = src[k * 3 + 1], x2 = src[k * 3 + 2];
        pt[i] = make_float3(x0, x1, x2);
        int q = (int)floorf((x0 - RLO) * INVBW);
        q = min(max(q, 0), NBUCKET - 1);
        bk[i] = q;
        atomicAdd(&sA[q], 1);
    }
    __syncthreads();

    // Hillis-Steele inclusive scan (10 iters, ping-pong) -> ends in sA
    int* pin = sA;
    int* pout = sB;
    for (int o = 1; o < NBUCKET; o <<= 1) {
        pout[tid] = pin[tid] + ((tid >= o) ? pin[tid - o] : 0);
        __syncthreads();
        int* t = pin; pin = pout; pout = t;
    }
    const int excl = tid ? pin[tid - 1] : 0;
    g_bstart[cloud][b][tid] = excl;
    if (tid == NBUCKET - 1) g_bstart[cloud][b][NBUCKET] = pin[NBUCKET - 1];

    // scatter via smem cursors (within-bucket order irrelevant: min is order-free)
    pout[tid] = excl;
    __syncthreads();
#pragma unroll
    for (int i = 0; i < 8; i++) {
        int pos = atomicAdd(&pout[bk[i]], 1);
        g_sorted[cloud][b][pos] = make_float4(pt[i].x, pt[i].y, pt[i].z, 0.f);
    }
}

// ---------------- K2: 160 small-loss blocks + 512 NN-query blocks ----------------
__global__ void __launch_bounds__(TPB, 8)
query_kernel(const float* __restrict__ pred, const float* __restrict__ targ) {
    __shared__ float  red[TPB];
    __shared__ float4 bufR[QSEG];
    __shared__ float4 bufL[QSEG];
    __shared__ int    sL, sR;

    const int tid = threadIdx.x;

    if (blockIdx.x < SL_BLOCKS) {
        // ======== small losses (proven R6 code, TPB=128) ========
        const int gid = blockIdx.x * TPB + tid;
        const int gsz = SL_BLOCKS * TPB;          // 20480

        const float4* p4 = (const float4*)pred;
        const float4* t4 = (const float4*)targ;
        float s = 0.f;
        for (int i = gid; i < B_ * N_ * 3 / 4; i += gsz) {
            float4 a = p4[i], bb = t4[i];
            float d0 = a.x - bb.x, d1 = a.y - bb.y, d2 = a.z - bb.z, d3 = a.w - bb.w;
            s = fmaf(d0, d0, fmaf(d1, d1, fmaf(d2, d2, fmaf(d3, d3, s))));
        }
        red[tid] = s; __syncthreads();
        for (int o = TPB / 2; o > 0; o >>= 1) {
            if (tid < o) red[tid] += red[tid + o];
            __syncthreads();
        }
        if (tid == 0) g_part[0 * SL_BLOCKS + blockIdx.x] = red[0];
        __syncthreads();

        s = 0.f;
        for (int b = 0; b < B_; b++) {
            const float* pb = pred + b * N_ * 3;
            for (int k = gid; k < N_ - 1; k += gsz) {
                const float* p = pb + k * 3;
                float dx = p[3] - p[0], dy = p[4] - p[1], dz = p[5] - p[2];
                s += sqrtf(fmaf(dx, dx, fmaf(dy, dy, dz * dz)));
            }
        }
        red[tid] = s; __syncthreads();
        for (int o = TPB / 2; o > 0; o >>= 1) {
            if (tid < o) red[tid] += red[tid + o];
            __syncthreads();
        }
        if (tid == 0) g_part[1 * SL_BLOCKS + blockIdx.x] = red[0];
        __syncthreads();

        s = 0.f;
        const int mid = N_ / 2;
        for (int b = 0; b < B_; b++) {
            const float* pb = pred + b * N_ * 3;
            for (int k = gid; k < mid; k += gsz) {
                const float* l = pb + k * 3;
                const float* r = pb + (N_ - 1 - k) * 3;
                float d0 = l[0] + r[0];
                float d1 = l[1] - r[1];
                float d2 = l[2] - r[2];
                s += fmaf(d0, d0, fmaf(d1, d1, d2 * d2));
            }
        }
        red[tid] = s; __syncthreads();
        for (int o = TPB / 2; o > 0; o >>= 1) {
            if (tid < o) red[tid] += red[tid + o];
            __syncthreads();
        }
        if (tid == 0) g_part[2 * SL_BLOCKS + blockIdx.x] = red[0];
        return;
    }

    // ======== exact NN query with bucketed axial pruning ========
    const int qb  = blockIdx.x - SL_BLOCKS;   // 0..511
    const int seg = qb & 63;                  // 64 segments of 128 queries
    const int b   = (qb >> 6) & 3;
    const int dir = qb >> 8;                  // 0: pred->targ, 1: targ->pred
    const float4* src    = g_sorted[dir][b];
    const float4* dst    = g_sorted[dir ^ 1][b];
    const int*    starts = g_bstart[dir ^ 1][b];

    const float4 q = src[seg * QSEG + tid];
    float best = 3.0e38f;
    bool doneL = false, doneR = false;

    if (tid == 0) {
        float midx = src[seg * QSEG + 64].x;
        int c = (int)floorf((midx - RLO) * INVBW);
        c = min(max(c, 0), NBUCKET - 1);
        int s0 = starts[c];
        sL = s0; sR = s0;                     // loaded region [sL, sR) empty
    }
    __syncthreads();

    for (int iter = 0; iter < 2 * (N_ / QSEG) + 4; iter++) {
        const int allR = __syncthreads_and((int)doneR);
        const int allL = __syncthreads_and((int)doneL);
        if (allR && allL) break;

        const int lo = sL, hi = sR;
        const int cntR = (!allR && hi < N_) ? min(QSEG, N_ - hi) : 0;
        const int cntL = (!allL && lo > 0)  ? min(QSEG, lo)      : 0;

        if (tid < cntR) bufR[tid] = dst[hi + tid];
        if (tid < cntL) bufL[tid] = dst[lo - cntL + tid];
        __syncthreads();
        if (tid == 0) { sL = lo - cntL; sR = hi + cntR; }

        // scan R chunk (skip only if whole warp is done on R)
        if (cntR > 0) {
            if (__ballot_sync(0xffffffffu, !doneR)) {
#pragma unroll 4
                for (int k = 0; k < cntR; k++) {
                    float4 p = bufR[k];
                    float dx = q.x - p.x, dy = q.y - p.y, dz = q.z - p.z;
                    float d2 = fmaf(dx, dx, fmaf(dy, dy, dz * dz));
                    best = fminf(best, d2);
                }
                // future R candidates have x0 >= bufR[cntR-1].x - BWID
                float fr = bufR[cntR - 1].x - BWID;
                float dr = fr - q.x;
                if (dr > 0.f && dr * dr > best) doneR = true;
            }
        }
        if (hi + cntR >= N_) doneR = true;    // R exhausted

        // scan L chunk
        if (cntL > 0) {
            if (__ballot_sync(0xffffffffu, !doneL)) {
#pragma unroll 4
                for (int k = 0; k < cntL; k++) {
                    float4 p = bufL[k];
                    float dx = q.x - p.x, dy = q.y - p.y, dz = q.z - p.z;
                    float d2 = fmaf(dx, dx, fmaf(dy, dy, dz * dz));
                    best = fminf(best, d2);
                }
                // future L candidates have x0 <= bufL[0].x + BWID
                float fl = bufL[0].x + BWID;
                float dl = q.x - fl;
                if (dl > 0.f && dl * dl > best) doneL = true;
            }
        }
        if (lo - cntL <= 0) doneL = true;     // L exhausted
    }

    // block sum of sqrt(min d2)
    red[tid] = sqrtf(best);
    __syncthreads();
    for (int o = TPB / 2; o > 0; o >>= 1) {
        if (tid < o) red[tid] += red[tid + o];
        __syncthreads();
    }
    if (tid == 0) g_qpart[qb] = red[0];
}

// ---------------- K3: final scalar ----------------
__global__ void final_kernel(float* __restrict__ out) {
    __shared__ float red[FTPB];
    __shared__ float sums[4];
    const int tid = threadIdx.x;

    float s = (tid < QBLOCKS) ? g_qpart[tid] : 0.f;
    red[tid] = s; __syncthreads();
    for (int o = FTPB / 2; o > 0; o >>= 1) {
        if (tid < o) red[tid] += red[tid + o];
        __syncthreads();
    }
    if (tid == 0) sums[3] = red[0];
    __syncthreads();

#pragma unroll
    for (int t = 0; t < 3; t++) {
        s = (tid < SL_BLOCKS) ? g_part[t * SL_BLOCKS + tid] : 0.f;
        red[tid] = s; __syncthreads();
        for (int o = FTPB / 2; o > 0; o >>= 1) {
            if (tid < o) red[tid] += red[tid + o];
            __syncthreads();
        }
        if (tid == 0) sums[t] = red[0];
        __syncthreads();
    }

    if (tid == 0) {
        float vertex_loss  = sums[0] / (float)(B_ * N_ * 3);
        float smooth_loss  = sums[1] / (float)(B_ * (N_ - 1));
        float sym_loss     = sums[2] / (float)(B_ * (N_ / 2) * 3);
        float chamfer_loss = sums[3] / (float)(B_ * N_);
        out[0] = 1.0f * vertex_loss + 0.1f * smooth_loss
               + 0.05f * sym_loss + 0.1f * chamfer_loss;
    }
}

extern "C" void kernel_launch(void* const* d_in, const int* in_sizes, int n_in,
                              void* d_out, int out_size) {
    const float* pred = (const float*)d_in[0];
    const float* targ = (const float*)d_in[1];
    float* out = (float*)d_out;
    (void)in_sizes; (void)n_in; (void)out_size;

    build_kernel<<<2 * B_, NBUCKET>>>(pred, targ);
    query_kernel<<<SL_BLOCKS + QBLOCKS, TPB>>>(pred, targ);
    final_kernel<<<1, FTPB>>>(out);
}

// round 9
// speedup vs baseline: 1.1210x; 1.1210x over previous
#include <cuda_runtime.h>
#include <math.h>

#define B_ 4
#define N_ 8192

constexpr int   NBUCKET = 1024;
constexpr float RLO   = -6.0f;
constexpr float BWID  = 12.0f / NBUCKET;
constexpr float INVBW = NBUCKET / 12.0f;

constexpr int BTPB      = 1024;                // build/SL launch block size
constexpr int BUILD_BLOCKS = 2 * B_;           // 8
constexpr int SL_BLOCKS = 56;                  // blocks 8..63 of build launch
constexpr int TPB       = 128;                 // query block size
constexpr int QSEG      = 128;                 // queries per block / chunk size
constexpr int QBLOCKS   = 2 * B_ * (N_ / QSEG);  // 512
constexpr int FTPB      = 512;

// Scratch (write-once per call; no init needed).
__device__ float4 g_sorted[2][B_][N_];             // bucket-ordered points
__device__ int    g_bstart[2][B_][NBUCKET + 1];    // bucket start offsets
__device__ float  g_part[3 * SL_BLOCKS];           // small-loss partials
__device__ float  g_qpart[QBLOCKS];                // per-block sum of sqrt(min d2)

// ---------------- K1: blocks 0-7 bucket build, blocks 8-63 small losses ----------------
__global__ void build_sl_kernel(const float* __restrict__ pred,
                                const float* __restrict__ targ) {
    __shared__ int sA[NBUCKET];
    __shared__ int sB[NBUCKET];
    const int tid = threadIdx.x;

    if (blockIdx.x < BUILD_BLOCKS) {
        // ======== counting sort by x0 (proven exact in R7) ========
        const int cloud = blockIdx.x >> 2;
        const int b     = blockIdx.x & 3;
        const float* src = (cloud ? targ : pred) + b * N_ * 3;

        sA[tid] = 0;
        __syncthreads();

        float3 pt[8];
        int    bk[8];
#pragma unroll
        for (int i = 0; i < 8; i++) {
            int k = tid + i * NBUCKET;
            float x0 = src[k * 3], x1 = src[k * 3 + 1], x2 = src[k * 3 + 2];
            pt[i] = make_float3(x0, x1, x2);
            int q = (int)floorf((x0 - RLO) * INVBW);
            q = min(max(q, 0), NBUCKET - 1);
            bk[i] = q;
            atomicAdd(&sA[q], 1);
        }
        __syncthreads();

        int* pin = sA;
        int* pout = sB;
        for (int o = 1; o < NBUCKET; o <<= 1) {
            pout[tid] = pin[tid] + ((tid >= o) ? pin[tid - o] : 0);
            __syncthreads();
            int* t = pin; pin = pout; pout = t;
        }
        const int excl = tid ? pin[tid - 1] : 0;
        g_bstart[cloud][b][tid] = excl;
        if (tid == NBUCKET - 1) g_bstart[cloud][b][NBUCKET] = pin[NBUCKET - 1];

        pout[tid] = excl;
        __syncthreads();
#pragma unroll
        for (int i = 0; i < 8; i++) {
            int pos = atomicAdd(&pout[bk[i]], 1);
            g_sorted[cloud][b][pos] = make_float4(pt[i].x, pt[i].y, pt[i].z, 0.f);
        }
        return;
    }

    // ======== small losses ========
    float* red = (float*)sA;   // reuse smem (4KB for 1024 floats)
    const int blk = blockIdx.x - BUILD_BLOCKS;
    const int gid = blk * BTPB + tid;
    const int gsz = SL_BLOCKS * BTPB;   // 57344

    const float4* p4 = (const float4*)pred;
    const float4* t4 = (const float4*)targ;
    float s = 0.f;
    for (int i = gid; i < B_ * N_ * 3 / 4; i += gsz) {
        float4 a = p4[i], bb = t4[i];
        float d0 = a.x - bb.x, d1 = a.y - bb.y, d2 = a.z - bb.z, d3 = a.w - bb.w;
        s = fmaf(d0, d0, fmaf(d1, d1, fmaf(d2, d2, fmaf(d3, d3, s))));
    }
    red[tid] = s; __syncthreads();
    for (int o = BTPB / 2; o > 0; o >>= 1) {
        if (tid < o) red[tid] += red[tid + o];
        __syncthreads();
    }
    if (tid == 0) g_part[0 * SL_BLOCKS + blk] = red[0];
    __syncthreads();

    s = 0.f;
    for (int b = 0; b < B_; b++) {
        const float* pb = pred + b * N_ * 3;
        for (int k = gid; k < N_ - 1; k += gsz) {
            const float* p = pb + k * 3;
            float dx = p[3] - p[0], dy = p[4] - p[1], dz = p[5] - p[2];
            s += sqrtf(fmaf(dx, dx, fmaf(dy, dy, dz * dz)));
        }
    }
    red[tid] = s; __syncthreads();
    for (int o = BTPB / 2; o > 0; o >>= 1) {
        if (tid < o) red[tid] += red[tid + o];
        __syncthreads();
    }
    if (tid == 0) g_part[1 * SL_BLOCKS + blk] = red[0];
    __syncthreads();

    s = 0.f;
    const int mid = N_ / 2;
    for (int b = 0; b < B_; b++) {
        const float* pb = pred + b * N_ * 3;
        for (int k = gid; k < mid; k += gsz) {
            const float* l = pb + k * 3;
            const float* r = pb + (N_ - 1 - k) * 3;
            float d0 = l[0] + r[0];
            float d1 = l[1] - r[1];
            float d2 = l[2] - r[2];
            s += fmaf(d0, d0, fmaf(d1, d1, d2 * d2));
        }
    }
    red[tid] = s; __syncthreads();
    for (int o = BTPB / 2; o > 0; o >>= 1) {
        if (tid < o) red[tid] += red[tid + o];
        __syncthreads();
    }
    if (tid == 0) g_part[2 * SL_BLOCKS + blk] = red[0];
}

// fixed-128 chunk scan, 4 independent accumulators (compile-time bound -> unrolled, ILP)
__device__ __forceinline__ float scan_chunk(const float4* __restrict__ buf,
                                            float4 q, float best) {
    float b0 = best, b1 = 3.0e38f, b2 = 3.0e38f, b3 = 3.0e38f;
#pragma unroll
    for (int k = 0; k < QSEG; k += 4) {
        float4 p0 = buf[k], p1 = buf[k + 1], p2 = buf[k + 2], p3 = buf[k + 3];
        float dx0 = q.x - p0.x, dy0 = q.y - p0.y, dz0 = q.z - p0.z;
        float dx1 = q.x - p1.x, dy1 = q.y - p1.y, dz1 = q.z - p1.z;
        float dx2 = q.x - p2.x, dy2 = q.y - p2.y, dz2 = q.z - p2.z;
        float dx3 = q.x - p3.x, dy3 = q.y - p3.y, dz3 = q.z - p3.z;
        b0 = fminf(b0, fmaf(dx0, dx0, fmaf(dy0, dy0, dz0 * dz0)));
        b1 = fminf(b1, fmaf(dx1, dx1, fmaf(dy1, dy1, dz1 * dz1)));
        b2 = fminf(b2, fmaf(dx2, dx2, fmaf(dy2, dy2, dz2 * dz2)));
        b3 = fminf(b3, fmaf(dx3, dx3, fmaf(dy3, dy3, dz3 * dz3)));
    }
    return fminf(fminf(b0, b1), fminf(b2, b3));
}

// ---------------- K2: exact NN query with bucketed axial pruning ----------------
__global__ void __launch_bounds__(TPB, 8)
query_kernel() {
    __shared__ float  red[TPB];
    __shared__ float4 bufR[QSEG];
    __shared__ float4 bufL[QSEG];
    __shared__ int    sL, sR;

    const int tid = threadIdx.x;
    const int qb  = blockIdx.x;               // 0..511
    const int seg = qb & 63;
    const int b   = (qb >> 6) & 3;
    const int dir = qb >> 8;
    const float4* src    = g_sorted[dir][b];
    const float4* dst    = g_sorted[dir ^ 1][b];
    const int*    starts = g_bstart[dir ^ 1][b];

    const float4 q = src[seg * QSEG + tid];
    float best = 3.0e38f;
    bool doneL = false, doneR = false;

    if (tid == 0) {
        float midx = src[seg * QSEG + 64].x;
        int c = (int)floorf((midx - RLO) * INVBW);
        c = min(max(c, 0), NBUCKET - 1);
        int s0 = starts[c];
        sL = s0; sR = s0;
    }
    __syncthreads();

    const float4 sentinel = make_float4(1.0e18f, 1.0e18f, 1.0e18f, 0.f);

    for (int iter = 0; iter < 2 * (N_ / QSEG) + 4; iter++) {
        const int allR = __syncthreads_and((int)doneR);
        const int allL = __syncthreads_and((int)doneL);
        if (allR && allL) break;

        const int lo = sL, hi = sR;
        const int cntR = (!allR && hi < N_) ? min(QSEG, N_ - hi) : 0;
        const int cntL = (!allL && lo > 0)  ? min(QSEG, lo)      : 0;

        // stage with sentinel padding -> scans have compile-time trip count
        if (cntR > 0) bufR[tid] = (tid < cntR) ? dst[hi + tid] : sentinel;
        if (cntL > 0) bufL[tid] = (tid < cntL) ? dst[lo - cntL + tid] : sentinel;
        __syncthreads();
        if (tid == 0) { sL = lo - cntL; sR = hi + cntR; }

        if (cntR > 0 && __ballot_sync(0xffffffffu, !doneR)) {
            best = scan_chunk(bufR, q, best);
            float fr = bufR[cntR - 1].x - BWID;   // future R: x >= fr
            float dr = fr - q.x;
            if (dr > 0.f && dr * dr > best) doneR = true;
        }
        if (hi + cntR >= N_) doneR = true;

        if (cntL > 0 && __ballot_sync(0xffffffffu, !doneL)) {
            best = scan_chunk(bufL, q, best);
            float fl = bufL[0].x + BWID;          // future L: x <= fl
            float dl = q.x - fl;
            if (dl > 0.f && dl * dl > best) doneL = true;
        }
        if (lo - cntL <= 0) doneL = true;
    }

    red[tid] = sqrtf(best);
    __syncthreads();
    for (int o = TPB / 2; o > 0; o >>= 1) {
        if (tid < o) red[tid] += red[tid + o];
        __syncthreads();
    }
    if (tid == 0) g_qpart[qb] = red[0];
}

// ---------------- K3: final scalar ----------------
__global__ void final_kernel(float* __restrict__ out) {
    __shared__ float red[FTPB];
    __shared__ float sums[4];
    const int tid = threadIdx.x;

    float s = (tid < QBLOCKS) ? g_qpart[tid] : 0.f;
    red[tid] = s; __syncthreads();
    for (int o = FTPB / 2; o > 0; o >>= 1) {
        if (tid < o) red[tid] += red[tid + o];
        __syncthreads();
    }
    if (tid == 0) sums[3] = red[0];
    __syncthreads();

#pragma unroll
    for (int t = 0; t < 3; t++) {
        s = (tid < SL_BLOCKS) ? g_part[t * SL_BLOCKS + tid] : 0.f;
        red[tid] = s; __syncthreads();
        for (int o = FTPB / 2; o > 0; o >>= 1) {
            if (tid < o) red[tid] += red[tid + o];
            __syncthreads();
        }
        if (tid == 0) sums[t] = red[0];
        __syncthreads();
    }

    if (tid == 0) {
        float vertex_loss  = sums[0] / (float)(B_ * N_ * 3);
        float smooth_loss  = sums[1] / (float)(B_ * (N_ - 1));
        float sym_loss     = sums[2] / (float)(B_ * (N_ / 2) * 3);
        float chamfer_loss = sums[3] / (float)(B_ * N_);
        out[0] = 1.0f * vertex_loss + 0.1f * smooth_loss
               + 0.05f * sym_loss + 0.1f * chamfer_loss;
    }
}

extern "C" void kernel_launch(void* const* d_in, const int* in_sizes, int n_in,
                              void* d_out, int out_size) {
    const float* pred = (const float*)d_in[0];
    const float* targ = (const float*)d_in[1];
    float* out = (float*)d_out;
    (void)in_sizes; (void)n_in; (void)out_size;

    build_sl_kernel<<<BUILD_BLOCKS + SL_BLOCKS, BTPB>>>(pred, targ);
    query_kernel<<<QBLOCKS, TPB>>>();
    final_kernel<<<1, FTPB>>>(out);
}